// round 9
// baseline (speedup 1.0000x reference)
#include <cuda_runtime.h>

#define BB 16
#define NN 64
#define AA 8400
#define CC 20
#define KK 13
#define BA (BB*AA)
#define BN (BB*NN)
#define GB 32                 // bins per axis (20 px bins over 640 px)
#define NBIN (GB*GB)
#define BININV 0.05f          // 1/20
#define WPB 4                 // warps (rows) per k_gather block

// ---------------- device scratch (no allocations allowed) ------------------
__device__ int   g_bincnt[NBIN];         // zero-init; restored to 0 each call
__device__ int   g_binstart[NBIN + 1];
__device__ int   g_binpos[NBIN];
__device__ int   g_bidx[AA];             // anchor ids grouped by bin
__device__ float2 g_banc[AA];            // anchor coords grouped by bin
__device__ unsigned long long g_bits[BA];   // pre-filter mask_pos bitmask over n
__device__ unsigned long long g_amax[BA];   // packed (ov_bits<<32 | 63-n) argmax key
__device__ int   g_cand[BN*KK];
__device__ float g_cov[BN*KK];
__device__ float g_cal[BN*KK];
__device__ int   g_cnt[BN];
__device__ float g_norm[BA];
__device__ int   g_lshift;               // 0: labels int32, 1: labels int64

__device__ __forceinline__ int binclamp(int v) { return v < 0 ? 0 : (v > GB-1 ? GB-1 : v); }
__device__ __forceinline__ int lblclamp(int v) { return v < 0 ? 0 : (v > CC-1 ? CC-1 : v); }
__device__ __forceinline__ int getlbl(const int* gl, int i, int shift) {
    return lblclamp(__ldg(&gl[i << shift]));
}

// filtered mask_pos bits: pure function of (bits, amax)
__device__ __forceinline__ unsigned long long filt_bits(unsigned long long bits,
                                                        unsigned long long amax) {
    if (__popcll(bits) > 1) {
        int bi = 63 - (int)(unsigned)(amax & 0xFFFFFFFFull);
        bits &= (1ULL << bi);
    }
    return bits;
}

// ---------------- K_init_count: init bits/amax + bin histogram + detect ----
__global__ __launch_bounds__(512) void k_init_count(const float* __restrict__ anc,
                                                    const int* __restrict__ gl) {
    int i = blockIdx.x * blockDim.x + threadIdx.x;
    if (i < BA) { g_bits[i] = 0ULL; g_amax[i] = 63ULL; }  // (ov=0, n=0)
    if (i < AA) {
        float2 ap = __ldg(&((const float2*)anc)[i]);
        int bx = binclamp((int)floorf(ap.x * BININV));
        int by = binclamp((int)floorf(ap.y * BININV));
        atomicAdd(&g_bincnt[by*GB + bx], 1);
    }
    // label dtype detection in block 0: int64 labels have all odd words == 0
    if (blockIdx.x == 0) {
        __shared__ int s_ok;
        if (threadIdx.x == 0) s_ok = 1;
        __syncthreads();
        if (__ldg(&gl[2 * threadIdx.x + 1]) != 0) s_ok = 0;
        __syncthreads();
        if (threadIdx.x == 0) g_lshift = s_ok;
    }
}

// ---------------- K_scanscatter: scan bins + scatter anchors (1 block) -----
// Restores g_bincnt to 0 for the next call (static zero-init covers call 0).
__global__ __launch_bounds__(NBIN) void k_scanscatter(const float* __restrict__ anc) {
    __shared__ int sc[NBIN];
    int tid = threadIdx.x;
    int c = g_bincnt[tid];
    g_bincnt[tid] = 0;                    // restore for next call
    sc[tid] = c;
    __syncthreads();
    for (int off = 1; off < NBIN; off <<= 1) {
        int v = (tid >= off) ? sc[tid - off] : 0;
        __syncthreads();
        sc[tid] += v;
        __syncthreads();
    }
    int excl = sc[tid] - c;
    g_binstart[tid] = excl;
    g_binpos[tid]   = excl;
    if (tid == NBIN-1) g_binstart[NBIN] = sc[tid];
    __syncthreads();
    for (int i = tid; i < AA; i += NBIN) {
        float2 ap = __ldg(&((const float2*)anc)[i]);
        int bx = binclamp((int)floorf(ap.x * BININV));
        int by = binclamp((int)floorf(ap.y * BININV));
        int p = atomicAdd(&g_binpos[by*GB + bx], 1);
        g_bidx[p] = i;
        g_banc[p] = ap;
    }
}

// ---------------- K_gather: warp-per-row sparse CIoU + exact top-13 --------
__global__ __launch_bounds__(32*WPB) void k_gather(
    const float* __restrict__ anc, const float* __restrict__ pdb,
    const int* __restrict__ gl, const float* __restrict__ gtb,
    const float* __restrict__ mgt, const float* __restrict__ ps)
{
    const unsigned FULL = 0xffffffffu;
    const int wid = threadIdx.x >> 5;
    const int lane = threadIdx.x & 31;
    const int row = blockIdx.x * WPB + wid;
    const int b = row >> 6, n = row & 63;

    if (__ldg(&mgt[row]) <= 0.0f) { if (lane == 0) g_cnt[row] = 0; return; }

    float4 g = __ldg(&((const float4*)gtb)[row]);
    const float gx1 = g.x, gy1 = g.y, gx2 = g.z, gy2 = g.w;
    const float w1 = gx2 - gx1, h1 = gy2 - gy1;
    const float area1 = w1 * h1;
    const float atan1 = atanf(w1 / (h1 + 1e-7f));
    const int lshift = g_lshift;
    const int lbl0 = getlbl(gl, row, lshift);
    const float inv_pi2_4 = 4.0f / (3.14159265358979323846f * 3.14159265358979323846f);

    const int bx0 = binclamp((int)floorf(gx1 * BININV));
    const int bx1 = binclamp((int)floorf(gx2 * BININV));
    const int by0 = binclamp((int)floorf(gy1 * BININV));
    const int by1 = binclamp((int)floorf(gy2 * BININV));

    const float4* __restrict__ pdb4 = &((const float4*)pdb)[(long long)b * AA];

    // per-lane sorted top-13 (key desc); ovl moves with key
    unsigned long long kv[KK];
    float ovl[KK];
#pragma unroll
    for (int i = 0; i < KK; i++) { kv[i] = 0ULL; ovl[i] = 0.0f; }

    for (int by = by0; by <= by1; ++by) {
        const int s = __ldg(&g_binstart[by*GB + bx0]);
        const int e = __ldg(&g_binstart[by*GB + bx1 + 1]);
        for (int j = s + lane; j < e; j += 32) {
            float2 ap = g_banc[j];
            float d = fminf(fminf(ap.x - gx1, ap.y - gy1), fminf(gx2 - ap.x, gy2 - ap.y));
            if (d > 1e-9f) {
                int a = g_bidx[j];
                float4 p = __ldg(&pdb4[a]);
                float iw = fmaxf(fminf(gx2, p.z) - fmaxf(gx1, p.x), 0.0f);
                float ih = fmaxf(fminf(gy2, p.w) - fmaxf(gy1, p.y), 0.0f);
                float inter = iw * ih;
                float w2 = p.z - p.x, h2 = p.w - p.y;
                float uni = area1 + w2 * h2 - inter + 1e-7f;
                float iou = inter / uni;
                float cw = fmaxf(gx2, p.z) - fminf(gx1, p.x);
                float ch = fmaxf(gy2, p.w) - fminf(gy1, p.y);
                float c2 = cw * cw + ch * ch + 1e-7f;
                float dx = (p.x + p.z - gx1 - gx2);
                float dy = (p.y + p.w - gy1 - gy2);
                float rho2 = (dx * dx + dy * dy) * 0.25f;
                float dv = atanf(w2 / (h2 + 1e-7f)) - atan1;
                float v = inv_pi2_4 * dv * dv;
                float alpha = v / (v - iou + (1.0f + 1e-7f));
                float ov = fmaxf(iou - (rho2 / c2 + v * alpha), 0.0f);

                if (ov > 0.0f) {
                    unsigned long long ak =
                        ((unsigned long long)__float_as_uint(ov) << 32) |
                        (unsigned long long)(unsigned)(63 - n);
                    atomicMax(&g_amax[b*AA + a], ak);
                    float sc = __ldg(&ps[((long long)(b*AA + a)) * CC + lbl0]);
                    float ov2 = ov * ov;
                    float align = sc * ov2 * ov2 * ov2;   // > 0
                    unsigned long long key =
                        ((unsigned long long)__float_as_uint(align) << 32) |
                        (unsigned long long)(0xFFFFFFFFu - (unsigned)a);
                    if (key > kv[KK-1]) {
                        kv[KK-1] = key; ovl[KK-1] = ov;
#pragma unroll
                        for (int i = KK-1; i > 0; --i) {
                            if (kv[i-1] < kv[i]) {
                                unsigned long long tk = kv[i-1]; kv[i-1] = kv[i]; kv[i] = tk;
                                float to = ovl[i-1]; ovl[i-1] = ovl[i]; ovl[i] = to;
                            }
                        }
                    }
                }
            }
        }
    }

    // ---- warp merge: global top-13 from per-lane sorted lists -------------
    int ptr = 0;
    unsigned long long my_sel = 0ULL;
    float my_selov = 0.0f;
    int sel_count = 0;
    for (int r = 0; r < KK; r++) {
        unsigned long long cand = (ptr < KK) ? kv[ptr] : 0ULL;
        unsigned long long best = cand;
        int bl = lane;
#pragma unroll
        for (int off = 16; off > 0; off >>= 1) {
            unsigned long long ok = __shfl_xor_sync(FULL, best, off);
            int ol = __shfl_xor_sync(FULL, bl, off);
            if (ok > best) { best = ok; bl = ol; }
        }
        if (best == 0ULL) break;
        float ovcur = ovl[ptr < KK ? ptr : KK-1];
        float bov = __shfl_sync(FULL, ovcur, bl);
        if (lane == bl) ptr++;
        if (lane == r) { my_sel = best; my_selov = bov; }
        sel_count++;
    }

    const int base = row * KK;
    int my_a = (int)(0xFFFFFFFFu - (unsigned)(my_sel & 0xFFFFFFFFull));
    if (lane < sel_count) {
        atomicOr(&g_bits[b*AA + my_a], 1ULL << n);
        g_cand[base + lane] = my_a;
        g_cov[base + lane] = my_selov;
        g_cal[base + lane] = __uint_as_float((unsigned)(my_sel >> 32));
    }

    int cnt = sel_count;
    if (sel_count < KK) {
        // jax top_k zero-fill: KK-sel_count smallest-index zero-align anchors;
        // bits only for picks inside the box. Parallel via 32-wide windows.
        int need = KK - sel_count;
        int base_a = 0;
        while (need > 0 && base_a < AA) {
            int a = base_a + lane;
            bool nonpos = (a < AA);
            for (int k = 0; k < sel_count; k++) {
                int ak = __shfl_sync(FULL, my_a, k);
                if (a == ak) nonpos = false;
            }
            unsigned mnp = __ballot_sync(FULL, nonpos);
            int myrank = __popc(mnp & ((1u << lane) - 1));
            bool picked = nonpos && (myrank < need);
            bool valid = false;
            if (picked) {
                float2 ap = __ldg(&((const float2*)anc)[a]);
                float d = fminf(fminf(ap.x - gx1, ap.y - gy1),
                                fminf(gx2 - ap.x, gy2 - ap.y));
                valid = d > 1e-9f;
            }
            unsigned mv = __ballot_sync(FULL, picked && valid);
            if (picked && valid) {
                int vrank = __popc(mv & ((1u << lane) - 1));
                atomicOr(&g_bits[b*AA + a], 1ULL << n);
                g_cand[base + cnt + vrank] = a;
                g_cov[base + cnt + vrank] = 0.0f;
                g_cal[base + cnt + vrank] = 0.0f;
            }
            cnt += __popc(mv);
            int taken = __popc(mnp); if (taken > need) taken = need;
            need -= taken;
            base_a += 32;
        }
    }
    if (lane == 0) g_cnt[row] = cnt;
}

// ---------------- K_rowstats: pos_align/pos_ov + norm scatter --------------
__global__ void k_rowstats() {
    int row = blockIdx.x * blockDim.x + threadIdx.x;
    if (row >= BN) return;
    int cnt = g_cnt[row];
    if (cnt == 0) return;
    int b = row >> 6, n = row & 63;
    int base = row * KK;
    float pa = 0.0f, po = 0.0f;
    for (int j = 0; j < cnt; j++) {
        int a = g_cand[base + j];
        unsigned long long fb = filt_bits(g_bits[b*AA + a], g_amax[b*AA + a]);
        if ((fb >> n) & 1ULL) {
            pa = fmaxf(pa, g_cal[base + j]);
            po = fmaxf(po, g_cov[base + j]);
        }
    }
    float inv = po / (pa + 1e-9f);
    for (int j = 0; j < cnt; j++) {
        int a = g_cand[base + j];
        unsigned long long fb = filt_bits(g_bits[b*AA + a], g_amax[b*AA + a]);
        if ((fb >> n) & 1ULL)
            g_norm[b*AA + a] = g_cal[base + j] * inv;
    }
}

// ---------------- K_out: all outputs ---------------------------------------
__global__ void k_out(const int* __restrict__ gl,
                      const float* __restrict__ gtb,
                      float* __restrict__ out)
{
    int i = blockIdx.x * blockDim.x + threadIdx.x;
    if (i >= BA) return;
    int b = i / AA;

    unsigned long long bits = filt_bits(g_bits[i], g_amax[i]);
    int fg  = bits ? 1 : 0;
    int tgt = fg ? (__ffsll((long long)bits) - 1) : 0;
    int lbl = getlbl(gl, b*NN + tgt, g_lshift);
    float4 gbx = __ldg(&((const float4*)gtb)[b*NN + tgt]);
    float norm = fg ? g_norm[i] : 0.0f;

    out[i] = (float)lbl;
    ((float4*)(out + BA))[i] = gbx;

    float buf[CC];
#pragma unroll
    for (int c = 0; c < CC; c++) buf[c] = 0.0f;
    if (fg) buf[lbl] = norm;
    float4* o = (float4*)(out + 5*BA + (long long)i * CC);
#pragma unroll
    for (int q = 0; q < CC/4; q++)
        o[q] = make_float4(buf[4*q], buf[4*q+1], buf[4*q+2], buf[4*q+3]);

    out[(5 + CC)*BA + i] = (float)fg;
    out[(6 + CC)*BA + i] = (float)tgt;
}

// ---------------- launcher ---------------------------------------------------
extern "C" void kernel_launch(void* const* d_in, const int* in_sizes, int n_in,
                              void* d_out, int out_size)
{
    const float* pd_scores = (const float*)d_in[0];
    const float* pd_bboxes = (const float*)d_in[1];
    const float* anc       = (const float*)d_in[2];
    const int*   gt_labels = (const int*)d_in[3];   // int32 OR int64 — detected
    const float* gt_bboxes = (const float*)d_in[4];
    const float* mask_gt   = (const float*)d_in[5];
    float* out = (float*)d_out;

    k_init_count<<<(BA + 511)/512, 512>>>(anc, gt_labels);
    k_scanscatter<<<1, NBIN>>>(anc);
    k_gather<<<BN/WPB, 32*WPB>>>(anc, pd_bboxes, gt_labels, gt_bboxes, mask_gt, pd_scores);
    k_rowstats<<<(BN + 255)/256, 256>>>();
    k_out<<<(BA + 255)/256, 256>>>(gt_labels, gt_bboxes, out);
}